// round 1
// baseline (speedup 1.0000x reference)
#include <cuda_runtime.h>
#include <cuda_bf16.h>
#include <math.h>

// Problem constants
#define B_  16
#define N_  50
#define H_  128
#define V_  40000
#define VM1 39999      // V-1 rows of b_emb / output columns
#define R_  (B_*N_)    // 800 rows

// ---------------- scratch (static __device__, no allocs) ----------------
__device__ float g_hidden[R_*H_];
__device__ float g_ein   [R_*H_];
__device__ float g_eout  [R_*H_];
__device__ float g_inputs[R_*2*H_];
__device__ float g_gi    [R_*3*H_];
__device__ float g_gh    [R_*3*H_];
__device__ float g_ht    [B_*H_];
__device__ float g_q1    [B_*H_];
__device__ float g_q2    [R_*H_];
__device__ float g_cat   [B_*2*H_];
__device__ float g_a     [B_*H_];
__device__ float g_hm    [R_*H_];
__device__ float g_qt    [R_*H_];
__device__ float g_qtpad [B_*64*H_];   // [b][n(64)][h], n==50 holds a[b], n>50 zero

// ---------------- small helpers ----------------
__device__ __forceinline__ float sigmoidf_(float x){ return 1.f/(1.f+expf(-x)); }

// ---------------- gather: hidden = emb[items] ----------------
__global__ void k_gather(const int* __restrict__ items, const float* __restrict__ emb,
                         float* __restrict__ hidden){
    int r = blockIdx.x, h = threadIdx.x;
    hidden[r*H_ + h] = emb[(size_t)items[r]*H_ + h];
}

// ---------------- generic small GEMM: out[r,j] = sum_k X[r,k]*W[j,k] + bias[j] ----------------
__global__ void k_gemm_tn(const float* __restrict__ X, const float* __restrict__ W,
                          const float* __restrict__ bias, float* __restrict__ out,
                          int R, int K, int J){
    __shared__ float xs[16][65];
    __shared__ float ws[16][65];
    int tid = threadIdx.x;
    int tr = tid >> 4, tc = tid & 15;
    int r0 = blockIdx.y << 6, j0 = blockIdx.x << 6;
    float acc[4][4] = {};
    for (int kc = 0; kc < K; kc += 16){
        for (int t = tid; t < 1024; t += 256){
            int rr = t >> 4, kk = t & 15;
            int r = r0 + rr;
            xs[kk][rr] = (r < R) ? X[(size_t)r*K + kc + kk] : 0.f;
        }
        for (int t = tid; t < 1024; t += 256){
            int jj = t >> 4, kk = t & 15;
            int j = j0 + jj;
            ws[kk][jj] = (j < J) ? W[(size_t)j*K + kc + kk] : 0.f;
        }
        __syncthreads();
        #pragma unroll
        for (int kk = 0; kk < 16; kk++){
            float xv[4], wv[4];
            #pragma unroll
            for (int i=0;i<4;i++) xv[i] = xs[kk][(tr<<2)+i];
            #pragma unroll
            for (int j=0;j<4;j++) wv[j] = ws[kk][(tc<<2)+j];
            #pragma unroll
            for (int i=0;i<4;i++)
                #pragma unroll
                for (int j=0;j<4;j++)
                    acc[i][j] = fmaf(xv[i], wv[j], acc[i][j]);
        }
        __syncthreads();
    }
    #pragma unroll
    for (int i=0;i<4;i++){
        int r = r0 + (tr<<2) + i;
        if (r >= R) continue;
        #pragma unroll
        for (int j=0;j<4;j++){
            int jj = j0 + (tc<<2) + j;
            if (jj < J) out[(size_t)r*J + jj] = acc[i][j] + (bias ? bias[jj] : 0.f);
        }
    }
}

// ---------------- graph propagation: inputs = [A_in@ein + b_iah , A_out@eout + b_oah] ----------------
__global__ void k_prop(const float* __restrict__ A, const float* __restrict__ ein,
                       const float* __restrict__ eout, const float* __restrict__ b_iah,
                       const float* __restrict__ b_oah, float* __restrict__ inputs){
    int r = blockIdx.x;                 // b*50+n
    int b = r / N_;
    int h = threadIdx.x;
    __shared__ float arow[2*N_];
    if (h < 2*N_) arow[h] = A[(size_t)r*2*N_ + h];
    __syncthreads();
    float sin = b_iah[h], sout = b_oah[h];
    #pragma unroll 5
    for (int m = 0; m < N_; m++){
        sin  = fmaf(arow[m],      ein [(b*N_+m)*H_ + h], sin);
        sout = fmaf(arow[N_+m],   eout[(b*N_+m)*H_ + h], sout);
    }
    inputs[(size_t)r*2*H_ + h]      = sin;
    inputs[(size_t)r*2*H_ + H_ + h] = sout;
}

// ---------------- GRU gates (in-place hidden update) ----------------
__global__ void k_gate(const float* __restrict__ gi, const float* __restrict__ gh,
                       float* __restrict__ hidden){
    int r = blockIdx.x, h = threadIdx.x;
    float i_r = gi[(size_t)r*3*H_ + h];
    float i_i = gi[(size_t)r*3*H_ + H_ + h];
    float i_n = gi[(size_t)r*3*H_ + 2*H_ + h];
    float h_r = gh[(size_t)r*3*H_ + h];
    float h_i = gh[(size_t)r*3*H_ + H_ + h];
    float h_n = gh[(size_t)r*3*H_ + 2*H_ + h];
    float rg = sigmoidf_(i_r + h_r);
    float ig = sigmoidf_(i_i + h_i);
    float ng = tanhf(i_n + rg * h_n);
    float hv = hidden[r*H_ + h];
    hidden[r*H_ + h] = ng + ig * (hv - ng);
}

// ---------------- ht = hidden[b, len-1] ----------------
__global__ void k_ht(const int* __restrict__ mask, const float* __restrict__ hidden,
                     float* __restrict__ ht){
    int b = blockIdx.x;
    __shared__ int len;
    if (threadIdx.x == 0){
        int s = 0;
        for (int n = 0; n < N_; n++) s += mask[b*N_+n];
        len = s;
    }
    __syncthreads();
    int h = threadIdx.x;
    ht[b*H_ + h] = hidden[(b*N_ + len - 1)*H_ + h];
}

// ---------------- alpha attention + cat = [avec, ht] ----------------
__global__ void k_alpha(const float* __restrict__ q1, const float* __restrict__ q2,
                        const float* __restrict__ w3, const int* __restrict__ mask,
                        const float* __restrict__ hidden, const float* __restrict__ ht,
                        float* __restrict__ cat){
    int b = blockIdx.x, tid = threadIdx.x;
    __shared__ float logits[N_];
    int warp = tid >> 5, lane = tid & 31;
    for (int n = warp; n < N_; n += 4){
        float s = 0.f;
        for (int hh = lane; hh < H_; hh += 32){
            float x = q1[b*H_+hh] + q2[(b*N_+n)*H_ + hh];
            s += sigmoidf_(x) * w3[hh];
        }
        for (int d = 16; d; d >>= 1) s += __shfl_xor_sync(0xffffffffu, s, d);
        if (lane == 0) logits[n] = s;
    }
    __syncthreads();
    float mx = -3.0e38f;
    for (int n = 0; n < N_; n++) if (mask[b*N_+n]) mx = fmaxf(mx, logits[n]);
    float denom = 0.f;
    for (int n = 0; n < N_; n++) if (mask[b*N_+n]) denom += expf(logits[n]-mx);
    int h = tid;
    float s = 0.f;
    for (int n = 0; n < N_; n++)
        if (mask[b*N_+n]) s = fmaf(expf(logits[n]-mx), hidden[(b*N_+n)*H_ + h], s);
    cat[b*2*H_ + h]      = s / denom;
    cat[b*2*H_ + H_ + h] = ht[b*H_ + h];
}

// ---------------- hm = hidden * mask ----------------
__global__ void k_maskmul(const float* __restrict__ hidden, const int* __restrict__ mask,
                          float* __restrict__ hm){
    int r = blockIdx.x, h = threadIdx.x;
    hm[r*H_ + h] = mask[r] ? hidden[r*H_ + h] : 0.f;
}

// ---------------- pack qt into padded layout, with a[b] as column 50 ----------------
__global__ void k_pack(const float* __restrict__ qt, const float* __restrict__ a,
                       float* __restrict__ qtpad){
    int b = blockIdx.x >> 6, n = blockIdx.x & 63, h = threadIdx.x;
    float v = 0.f;
    if (n < N_)       v = qt[(b*N_+n)*H_ + h];
    else if (n == N_) v = a[b*H_ + h];
    qtpad[((size_t)b*64 + n)*H_ + h] = v;
}

// ---------------- fused vocab scoring: L = emb_tile @ qtpad_b^T, masked softmax epilogue ----------------
// grid: (ceil(VM1/128), B), block 128 threads, 8x8 register tile per thread.
__global__ void k_scores(const float* __restrict__ emb, const float* __restrict__ qtpad,
                         const int* __restrict__ mask, float* __restrict__ out){
    __shared__ float qsm[64*129];      // [n][k], padded stride 129
    __shared__ float esm[128*17];      // [v][k-chunk], padded stride 17
    __shared__ int   msk[64];
    const int b  = blockIdx.y;
    const int v0 = blockIdx.x << 7;    // 128 vocab rows per block (b_emb index)
    const int tid = threadIdx.x;
    const int tv = tid >> 3;           // 0..15  (v = tv + 16*i)
    const int tn = tid & 7;            // 0..7   (n = tn + 8*j)

    // load qtpad[b] (64x128) into smem with +1 padded rows
    {
        const float4* qb = reinterpret_cast<const float4*>(qtpad + (size_t)b*64*H_);
        for (int t = tid; t < 2048; t += 128){
            int n = t >> 5;
            int c = (t & 31) << 2;
            float4 val = qb[t];
            qsm[n*129 + c + 0] = val.x;
            qsm[n*129 + c + 1] = val.y;
            qsm[n*129 + c + 2] = val.z;
            qsm[n*129 + c + 3] = val.w;
        }
        if (tid < 64) msk[tid] = (tid < N_) ? mask[b*N_ + tid] : 0;
    }

    float acc[8][8] = {};
    for (int kc = 0; kc < H_; kc += 16){
        // stage emb tile (128 x 16)
        for (int t = tid; t < 512; t += 128){
            int row = t >> 2;
            int c4  = (t & 3) << 2;
            float4 val = make_float4(0.f,0.f,0.f,0.f);
            int vg = v0 + row;                 // b_emb row index
            if (vg < VM1)
                val = *reinterpret_cast<const float4*>(emb + (size_t)(vg+1)*H_ + kc + c4);
            esm[row*17 + c4 + 0] = val.x;
            esm[row*17 + c4 + 1] = val.y;
            esm[row*17 + c4 + 2] = val.z;
            esm[row*17 + c4 + 3] = val.w;
        }
        __syncthreads();
        #pragma unroll
        for (int kk = 0; kk < 16; kk++){
            float ev[8], qv[8];
            #pragma unroll
            for (int i = 0; i < 8; i++) ev[i] = esm[(tv + (i<<4))*17 + kk];
            #pragma unroll
            for (int j = 0; j < 8; j++) qv[j] = qsm[(tn + (j<<3))*129 + kc + kk];
            #pragma unroll
            for (int i = 0; i < 8; i++)
                #pragma unroll
                for (int j = 0; j < 8; j++)
                    acc[i][j] = fmaf(ev[i], qv[j], acc[i][j]);
        }
        __syncthreads();
    }

    // epilogue: per v-row, masked softmax over n<50 then weighted sum + a-dot (col 50)
    const int lane  = tid & 31;
    const int gbase = lane & ~7;
    #pragma unroll
    for (int i = 0; i < 8; i++){
        float adot = __shfl_sync(0xffffffffu, acc[i][6], gbase + 2);  // n = 2+48 = 50
        float mx = -3.0e38f;
        #pragma unroll
        for (int j = 0; j < 8; j++){
            int n = tn + (j<<3);
            if (n < N_ && msk[n]) mx = fmaxf(mx, acc[i][j]);
        }
        mx = fmaxf(mx, __shfl_xor_sync(0xffffffffu, mx, 1));
        mx = fmaxf(mx, __shfl_xor_sync(0xffffffffu, mx, 2));
        mx = fmaxf(mx, __shfl_xor_sync(0xffffffffu, mx, 4));
        float se = 0.f, sw = 0.f;
        #pragma unroll
        for (int j = 0; j < 8; j++){
            int n = tn + (j<<3);
            if (n < N_ && msk[n]){
                float e = __expf(acc[i][j] - mx);
                se += e;
                sw = fmaf(e, acc[i][j], sw);
            }
        }
        se += __shfl_xor_sync(0xffffffffu, se, 1);
        sw += __shfl_xor_sync(0xffffffffu, sw, 1);
        se += __shfl_xor_sync(0xffffffffu, se, 2);
        sw += __shfl_xor_sync(0xffffffffu, sw, 2);
        se += __shfl_xor_sync(0xffffffffu, se, 4);
        sw += __shfl_xor_sync(0xffffffffu, sw, 4);
        if (tn == 0){
            int v = v0 + tv + (i<<4);
            if (v < VM1) out[(size_t)b*VM1 + v] = sw/se + adot;
        }
    }
}

// ---------------- host side ----------------
static float* symaddr(const void* sym){
    void* p = nullptr;
    cudaGetSymbolAddress(&p, sym);
    return (float*)p;
}

static void gemm(const float* X, const float* W, const float* bias, float* out,
                 int R, int K, int J){
    dim3 g((J + 63) / 64, (R + 63) / 64);
    k_gemm_tn<<<g, 256>>>(X, W, bias, out, R, K, J);
}

extern "C" void kernel_launch(void* const* d_in, const int* in_sizes, int n_in,
                              void* d_out, int out_size){
    (void)in_sizes; (void)n_in; (void)out_size;
    const int*   items  = (const int*)  d_in[0];
    const float* A      = (const float*)d_in[1];
    const int*   mask   = (const int*)  d_in[2];
    const float* emb    = (const float*)d_in[3];
    const float* w_ih   = (const float*)d_in[4];
    const float* w_hh   = (const float*)d_in[5];
    const float* b_ih   = (const float*)d_in[6];
    const float* b_hh   = (const float*)d_in[7];
    const float* b_iah  = (const float*)d_in[8];
    const float* b_oah  = (const float*)d_in[9];
    const float* W_ein  = (const float*)d_in[10];
    const float* b_ein  = (const float*)d_in[11];
    const float* W_eout = (const float*)d_in[12];
    const float* b_eout = (const float*)d_in[13];
    const float* W_one  = (const float*)d_in[14];
    const float* b_one  = (const float*)d_in[15];
    const float* W_two  = (const float*)d_in[16];
    const float* b_two  = (const float*)d_in[17];
    const float* w_three= (const float*)d_in[18];
    const float* W_tr   = (const float*)d_in[19];
    const float* b_tr   = (const float*)d_in[20];
    const float* W_t    = (const float*)d_in[21];
    float* out = (float*)d_out;

    float* hidden = symaddr(g_hidden);
    float* ein    = symaddr(g_ein);
    float* eout   = symaddr(g_eout);
    float* inputs = symaddr(g_inputs);
    float* gi     = symaddr(g_gi);
    float* gh     = symaddr(g_gh);
    float* ht     = symaddr(g_ht);
    float* q1     = symaddr(g_q1);
    float* q2     = symaddr(g_q2);
    float* cat    = symaddr(g_cat);
    float* a      = symaddr(g_a);
    float* hm     = symaddr(g_hm);
    float* qt     = symaddr(g_qt);
    float* qtpad  = symaddr(g_qtpad);

    // embedding gather
    k_gather<<<R_, H_>>>(items, emb, hidden);

    // 2 GNN steps
    for (int step = 0; step < 2; step++){
        gemm(hidden, W_ein,  b_ein,  ein,  R_, H_,   H_);
        gemm(hidden, W_eout, b_eout, eout, R_, H_,   H_);
        k_prop<<<R_, H_>>>(A, ein, eout, b_iah, b_oah, inputs);
        gemm(inputs, w_ih, b_ih, gi, R_, 2*H_, 3*H_);
        gemm(hidden, w_hh, b_hh, gh, R_, H_,   3*H_);
        k_gate<<<R_, H_>>>(gi, gh, hidden);
    }

    // attention head
    k_ht<<<B_, H_>>>(mask, hidden, ht);
    gemm(ht,     W_one, b_one, q1, B_, H_, H_);
    gemm(hidden, W_two, b_two, q2, R_, H_, H_);
    k_alpha<<<B_, H_>>>(q1, q2, w_three, mask, hidden, ht, cat);
    gemm(cat, W_tr, b_tr, a, B_, 2*H_, H_);
    k_maskmul<<<R_, H_>>>(hidden, mask, hm);
    gemm(hm, W_t, nullptr, qt, R_, H_, H_);
    k_pack<<<B_*64, H_>>>(qt, a, qtpad);

    // fused vocab scoring
    dim3 sg((VM1 + 127) / 128, B_);
    k_scores<<<sg, 128>>>(emb, qtpad, mask, out);
}

// round 3
// speedup vs baseline: 1.7091x; 1.7091x over previous
#include <cuda_runtime.h>
#include <cuda_bf16.h>
#include <math.h>

// Problem constants
#define B_  16
#define N_  50
#define H_  128
#define V_  40000
#define VM1 39999      // V-1 rows of b_emb / output columns
#define R_  (B_*N_)    // 800 rows

// ---------------- scratch (static __device__, no allocs) ----------------
__device__ float g_hidden[R_*H_];
__device__ float g_ein   [R_*H_];
__device__ float g_eout  [R_*H_];
__device__ float g_inputs[R_*2*H_];
__device__ float g_ht    [B_*H_];
__device__ float g_q1    [B_*H_];
__device__ float g_q2    [R_*H_];
__device__ float g_cat   [B_*2*H_];
__device__ float g_a     [B_*H_];
__device__ float g_hm    [R_*H_];
__device__ float g_qt    [R_*H_];
__device__ float g_qtpad [B_*64*H_];   // [b][n(64)][h], n==50 holds a[b], n>50 zero

// ---------------- small helpers ----------------
__device__ __forceinline__ float sigmoidf_(float x){ return 1.f/(1.f+expf(-x)); }

__device__ __forceinline__ unsigned long long pack2(float x, float y){
    unsigned long long r;
    asm("mov.b64 %0, {%1, %2};" : "=l"(r) : "f"(x), "f"(y));
    return r;
}
__device__ __forceinline__ unsigned long long fma2(unsigned long long a,
                                                   unsigned long long b,
                                                   unsigned long long c){
    unsigned long long d;
    asm("fma.rn.f32x2 %0, %1, %2, %3;" : "=l"(d) : "l"(a), "l"(b), "l"(c));
    return d;
}
__device__ __forceinline__ float lo2(unsigned long long u){
    return __uint_as_float((unsigned)(u & 0xffffffffULL));
}
__device__ __forceinline__ float hi2(unsigned long long u){
    return __uint_as_float((unsigned)(u >> 32));
}

// ---------------- gather: hidden = emb[items] ----------------
__global__ void k_gather(const int* __restrict__ items, const float* __restrict__ emb,
                         float* __restrict__ hidden){
    int r = blockIdx.x, h = threadIdx.x;
    hidden[r*H_ + h] = emb[(size_t)items[r]*H_ + h];
}

// ---------------- generic small GEMM: out[r,j] = sum_k X[r,k]*W[j,k] + bias[j] ----------------
__global__ void k_gemm_tn(const float* __restrict__ X, const float* __restrict__ W,
                          const float* __restrict__ bias, float* __restrict__ out,
                          int R, int K, int J){
    __shared__ float xs[16][65];
    __shared__ float ws[16][65];
    int tid = threadIdx.x;
    int tr = tid >> 4, tc = tid & 15;
    int r0 = blockIdx.y << 6, j0 = blockIdx.x << 6;
    float acc[4][4] = {};
    for (int kc = 0; kc < K; kc += 16){
        for (int t = tid; t < 1024; t += 256){
            int rr = t >> 4, kk = t & 15;
            int r = r0 + rr;
            xs[kk][rr] = (r < R) ? X[(size_t)r*K + kc + kk] : 0.f;
        }
        for (int t = tid; t < 1024; t += 256){
            int jj = t >> 4, kk = t & 15;
            int j = j0 + jj;
            ws[kk][jj] = (j < J) ? W[(size_t)j*K + kc + kk] : 0.f;
        }
        __syncthreads();
        #pragma unroll
        for (int kk = 0; kk < 16; kk++){
            float xv[4], wv[4];
            #pragma unroll
            for (int i=0;i<4;i++) xv[i] = xs[kk][(tr<<2)+i];
            #pragma unroll
            for (int j=0;j<4;j++) wv[j] = ws[kk][(tc<<2)+j];
            #pragma unroll
            for (int i=0;i<4;i++)
                #pragma unroll
                for (int j=0;j<4;j++)
                    acc[i][j] = fmaf(xv[i], wv[j], acc[i][j]);
        }
        __syncthreads();
    }
    #pragma unroll
    for (int i=0;i<4;i++){
        int r = r0 + (tr<<2) + i;
        if (r >= R) continue;
        #pragma unroll
        for (int j=0;j<4;j++){
            int jj = j0 + (tc<<2) + j;
            if (jj < J) out[(size_t)r*J + jj] = acc[i][j] + (bias ? bias[jj] : 0.f);
        }
    }
}

// ---------------- fused two-output GEMM for ein/eout (R=800, K=J=128) ----------------
__global__ void k_gemm2(const float* __restrict__ X,
                        const float* __restrict__ W1, const float* __restrict__ b1,
                        const float* __restrict__ W2, const float* __restrict__ b2,
                        float* __restrict__ out1, float* __restrict__ out2){
    __shared__ float xs [16][65];
    __shared__ float ws1[16][65];
    __shared__ float ws2[16][65];
    int tid = threadIdx.x;
    int tr = tid >> 4, tc = tid & 15;
    int r0 = blockIdx.y << 6, j0 = blockIdx.x << 6;
    float acc1[4][4] = {}, acc2_[4][4] = {};
    for (int kc = 0; kc < H_; kc += 16){
        for (int t = tid; t < 1024; t += 256){
            int rr = t >> 4, kk = t & 15;
            int r = r0 + rr;
            xs[kk][rr] = (r < R_) ? X[(size_t)r*H_ + kc + kk] : 0.f;
        }
        for (int t = tid; t < 1024; t += 256){
            int jj = t >> 4, kk = t & 15;
            ws1[kk][jj] = W1[(size_t)(j0+jj)*H_ + kc + kk];
            ws2[kk][jj] = W2[(size_t)(j0+jj)*H_ + kc + kk];
        }
        __syncthreads();
        #pragma unroll
        for (int kk = 0; kk < 16; kk++){
            float xv[4], w1v[4], w2v[4];
            #pragma unroll
            for (int i=0;i<4;i++) xv[i] = xs[kk][(tr<<2)+i];
            #pragma unroll
            for (int j=0;j<4;j++){ w1v[j] = ws1[kk][(tc<<2)+j]; w2v[j] = ws2[kk][(tc<<2)+j]; }
            #pragma unroll
            for (int i=0;i<4;i++)
                #pragma unroll
                for (int j=0;j<4;j++){
                    acc1[i][j]  = fmaf(xv[i], w1v[j], acc1[i][j]);
                    acc2_[i][j] = fmaf(xv[i], w2v[j], acc2_[i][j]);
                }
        }
        __syncthreads();
    }
    #pragma unroll
    for (int i=0;i<4;i++){
        int r = r0 + (tr<<2) + i;
        if (r >= R_) continue;
        #pragma unroll
        for (int j=0;j<4;j++){
            int jj = j0 + (tc<<2) + j;
            out1[(size_t)r*H_ + jj] = acc1[i][j]  + b1[jj];
            out2[(size_t)r*H_ + jj] = acc2_[i][j] + b2[jj];
        }
    }
}

// ---------------- graph propagation ----------------
__global__ void k_prop(const float* __restrict__ A, const float* __restrict__ ein,
                       const float* __restrict__ eout, const float* __restrict__ b_iah,
                       const float* __restrict__ b_oah, float* __restrict__ inputs){
    int r = blockIdx.x;                 // b*50+n
    int b = r / N_;
    int h = threadIdx.x;
    __shared__ float arow[2*N_];
    if (h < 2*N_) arow[h] = A[(size_t)r*2*N_ + h];
    __syncthreads();
    float sin = b_iah[h], sout = b_oah[h];
    #pragma unroll 5
    for (int m = 0; m < N_; m++){
        sin  = fmaf(arow[m],      ein [(b*N_+m)*H_ + h], sin);
        sout = fmaf(arow[N_+m],   eout[(b*N_+m)*H_ + h], sout);
    }
    inputs[(size_t)r*2*H_ + h]      = sin;
    inputs[(size_t)r*2*H_ + H_ + h] = sout;
}

// ---------------- fused GRU: gi + gh + gate, in-place hidden update ----------------
// grid = 100 blocks (8 rows each), 256 threads. warp w owns row r0+w; lanes own 4 h each.
__global__ void k_gru(const float* __restrict__ inputs, float* __restrict__ hidden,
                      const float* __restrict__ w_ih, const float* __restrict__ w_hh,
                      const float* __restrict__ b_ih, const float* __restrict__ b_hh){
    __shared__ __align__(16) float ws[48*132];   // [g*16+kk][h]
    __shared__ float xs[16*9];                   // [kk][r]
    const int tid = threadIdx.x;
    const int r   = tid >> 5;            // 0..7 (warp == row)
    const int h0  = (tid & 31) << 2;     // 0..124
    const int r0  = blockIdx.x << 3;

    float sr[4], si[4], an[4], hn[4];
    #pragma unroll
    for (int j = 0; j < 4; j++){
        int h = h0 + j;
        sr[j] = b_ih[h]       + b_hh[h];
        si[j] = b_ih[H_+h]    + b_hh[H_+h];
        an[j] = b_ih[2*H_+h];
        hn[j] = b_hh[2*H_+h];
    }

    // ---- phase A: gi accumulation, K = 2H = 256 ----
    for (int kc = 0; kc < 2*H_; kc += 16){
        #pragma unroll
        for (int it = 0; it < 6; it++){
            int idx = tid + (it << 8);          // 0..1535
            int row = idx >> 2;                 // 0..383
            int kq  = idx & 3;
            float4 w = *reinterpret_cast<const float4*>(w_ih + (size_t)row*2*H_ + kc + (kq<<2));
            int g = row >> 7, h = row & 127;
            ws[((g<<4) + (kq<<2) + 0)*132 + h] = w.x;
            ws[((g<<4) + (kq<<2) + 1)*132 + h] = w.y;
            ws[((g<<4) + (kq<<2) + 2)*132 + h] = w.z;
            ws[((g<<4) + (kq<<2) + 3)*132 + h] = w.w;
        }
        if (tid < 32){
            int rr = tid >> 2, kq = tid & 3;
            float4 x = *reinterpret_cast<const float4*>(inputs + (size_t)(r0+rr)*2*H_ + kc + (kq<<2));
            xs[((kq<<2)+0)*9 + rr] = x.x;
            xs[((kq<<2)+1)*9 + rr] = x.y;
            xs[((kq<<2)+2)*9 + rr] = x.z;
            xs[((kq<<2)+3)*9 + rr] = x.w;
        }
        __syncthreads();
        #pragma unroll
        for (int kk = 0; kk < 16; kk++){
            float xv = xs[kk*9 + r];
            float4 wr = *reinterpret_cast<const float4*>(&ws[( 0 + kk)*132 + h0]);
            float4 wi = *reinterpret_cast<const float4*>(&ws[(16 + kk)*132 + h0]);
            float4 wn = *reinterpret_cast<const float4*>(&ws[(32 + kk)*132 + h0]);
            sr[0]=fmaf(xv,wr.x,sr[0]); sr[1]=fmaf(xv,wr.y,sr[1]); sr[2]=fmaf(xv,wr.z,sr[2]); sr[3]=fmaf(xv,wr.w,sr[3]);
            si[0]=fmaf(xv,wi.x,si[0]); si[1]=fmaf(xv,wi.y,si[1]); si[2]=fmaf(xv,wi.z,si[2]); si[3]=fmaf(xv,wi.w,si[3]);
            an[0]=fmaf(xv,wn.x,an[0]); an[1]=fmaf(xv,wn.y,an[1]); an[2]=fmaf(xv,wn.z,an[2]); an[3]=fmaf(xv,wn.w,an[3]);
        }
        __syncthreads();
    }

    // ---- phase B: gh accumulation, K = H = 128 ----
    for (int kc = 0; kc < H_; kc += 16){
        #pragma unroll
        for (int it = 0; it < 6; it++){
            int idx = tid + (it << 8);
            int row = idx >> 2;
            int kq  = idx & 3;
            float4 w = *reinterpret_cast<const float4*>(w_hh + (size_t)row*H_ + kc + (kq<<2));
            int g = row >> 7, h = row & 127;
            ws[((g<<4) + (kq<<2) + 0)*132 + h] = w.x;
            ws[((g<<4) + (kq<<2) + 1)*132 + h] = w.y;
            ws[((g<<4) + (kq<<2) + 2)*132 + h] = w.z;
            ws[((g<<4) + (kq<<2) + 3)*132 + h] = w.w;
        }
        if (tid < 32){
            int rr = tid >> 2, kq = tid & 3;
            float4 x = *reinterpret_cast<const float4*>(hidden + (size_t)(r0+rr)*H_ + kc + (kq<<2));
            xs[((kq<<2)+0)*9 + rr] = x.x;
            xs[((kq<<2)+1)*9 + rr] = x.y;
            xs[((kq<<2)+2)*9 + rr] = x.z;
            xs[((kq<<2)+3)*9 + rr] = x.w;
        }
        __syncthreads();
        #pragma unroll
        for (int kk = 0; kk < 16; kk++){
            float xv = xs[kk*9 + r];
            float4 wr = *reinterpret_cast<const float4*>(&ws[( 0 + kk)*132 + h0]);
            float4 wi = *reinterpret_cast<const float4*>(&ws[(16 + kk)*132 + h0]);
            float4 wn = *reinterpret_cast<const float4*>(&ws[(32 + kk)*132 + h0]);
            sr[0]=fmaf(xv,wr.x,sr[0]); sr[1]=fmaf(xv,wr.y,sr[1]); sr[2]=fmaf(xv,wr.z,sr[2]); sr[3]=fmaf(xv,wr.w,sr[3]);
            si[0]=fmaf(xv,wi.x,si[0]); si[1]=fmaf(xv,wi.y,si[1]); si[2]=fmaf(xv,wi.z,si[2]); si[3]=fmaf(xv,wi.w,si[3]);
            hn[0]=fmaf(xv,wn.x,hn[0]); hn[1]=fmaf(xv,wn.y,hn[1]); hn[2]=fmaf(xv,wn.z,hn[2]); hn[3]=fmaf(xv,wn.w,hn[3]);
        }
        __syncthreads();
    }

    // ---- gate epilogue ----
    #pragma unroll
    for (int j = 0; j < 4; j++){
        float rg = sigmoidf_(sr[j]);
        float ig = sigmoidf_(si[j]);
        float ng = tanhf(an[j] + rg * hn[j]);
        float hv = hidden[(size_t)(r0+r)*H_ + h0 + j];
        hidden[(size_t)(r0+r)*H_ + h0 + j] = ng + ig * (hv - ng);
    }
}

// ---------------- ht = hidden[b, len-1] ----------------
__global__ void k_ht(const int* __restrict__ mask, const float* __restrict__ hidden,
                     float* __restrict__ ht){
    int b = blockIdx.x;
    __shared__ int len;
    if (threadIdx.x == 0){
        int s = 0;
        for (int n = 0; n < N_; n++) s += mask[b*N_+n];
        len = s;
    }
    __syncthreads();
    int h = threadIdx.x;
    ht[b*H_ + h] = hidden[(b*N_ + len - 1)*H_ + h];
}

// ---------------- alpha attention + cat = [avec, ht] ----------------
__global__ void k_alpha(const float* __restrict__ q1, const float* __restrict__ q2,
                        const float* __restrict__ w3, const int* __restrict__ mask,
                        const float* __restrict__ hidden, const float* __restrict__ ht,
                        float* __restrict__ cat){
    int b = blockIdx.x, tid = threadIdx.x;
    __shared__ float logits[N_];
    int warp = tid >> 5, lane = tid & 31;
    for (int n = warp; n < N_; n += 4){
        float s = 0.f;
        for (int hh = lane; hh < H_; hh += 32){
            float x = q1[b*H_+hh] + q2[(b*N_+n)*H_ + hh];
            s += sigmoidf_(x) * w3[hh];
        }
        for (int d = 16; d; d >>= 1) s += __shfl_xor_sync(0xffffffffu, s, d);
        if (lane == 0) logits[n] = s;
    }
    __syncthreads();
    float mx = -3.0e38f;
    for (int n = 0; n < N_; n++) if (mask[b*N_+n]) mx = fmaxf(mx, logits[n]);
    float denom = 0.f;
    for (int n = 0; n < N_; n++) if (mask[b*N_+n]) denom += expf(logits[n]-mx);
    int h = tid;
    float s = 0.f;
    for (int n = 0; n < N_; n++)
        if (mask[b*N_+n]) s = fmaf(expf(logits[n]-mx), hidden[(b*N_+n)*H_ + h], s);
    cat[b*2*H_ + h]      = s / denom;
    cat[b*2*H_ + H_ + h] = ht[b*H_ + h];
}

// ---------------- hm = hidden * mask ----------------
__global__ void k_maskmul(const float* __restrict__ hidden, const int* __restrict__ mask,
                          float* __restrict__ hm){
    int r = blockIdx.x, h = threadIdx.x;
    hm[r*H_ + h] = mask[r] ? hidden[r*H_ + h] : 0.f;
}

// ---------------- pack qt into padded layout, with a[b] as column 50 ----------------
__global__ void k_pack(const float* __restrict__ qt, const float* __restrict__ a,
                       float* __restrict__ qtpad){
    int b = blockIdx.x >> 6, n = blockIdx.x & 63, h = threadIdx.x;
    float v = 0.f;
    if (n < N_)       v = qt[(b*N_+n)*H_ + h];
    else if (n == N_) v = a[b*H_ + h];
    qtpad[((size_t)b*64 + n)*H_ + h] = v;
}

// ---------------- fused vocab scoring with f32x2 packed FMA ----------------
// grid (313, 16), block 128. Tile 128 v x 64 n. Thread tile 8v x 8n (as 8 x 4 float2).
// qs: [k][n] k-major, es: [kk][v] k-major, emb chunk double-buffered through regs.
__global__ void __launch_bounds__(128, 4)
k_scores(const float* __restrict__ emb, const float* __restrict__ qtpad,
         const int* __restrict__ mask, float* __restrict__ out){
    __shared__ __align__(16) float qs[H_*68];       // [k][n], stride 68
    __shared__ __align__(16) float es[2][16*132];   // [kk][v], stride 132
    __shared__ int msk[64];
    const int b   = blockIdx.y;
    const int v0  = blockIdx.x << 7;
    const int tid = threadIdx.x;
    const int tv  = tid >> 3;        // 0..15
    const int tn  = tid & 7;         // 0..7

    // ---- stage q (k-major transpose): thread: n = tid&63, k-half = tid>>6 ----
    {
        const float* qb = qtpad + (size_t)b*64*H_;
        int n = tid & 63, kh = tid >> 6;
        const float4* src = reinterpret_cast<const float4*>(qb + n*H_ + kh*64);
        #pragma unroll
        for (int i = 0; i < 16; i++){
            float4 v = src[i];
            int k = kh*64 + (i<<2);
            qs[(k+0)*68+n]=v.x; qs[(k+1)*68+n]=v.y; qs[(k+2)*68+n]=v.z; qs[(k+3)*68+n]=v.w;
        }
        if (tid < 64) msk[tid] = (tid < N_) ? mask[b*N_ + tid] : 0;
    }

    // ---- emb row for this thread ----
    const int vg  = v0 + tid;
    const bool vok = vg < VM1;
    const float* erow = emb + (size_t)(vg+1)*H_;
    float rbuf[16];

    // prologue: chunk 0 -> regs -> es[0]
    #pragma unroll
    for (int q4 = 0; q4 < 4; q4++){
        float4 t = vok ? *reinterpret_cast<const float4*>(erow + (q4<<2))
                       : make_float4(0.f,0.f,0.f,0.f);
        rbuf[q4*4+0]=t.x; rbuf[q4*4+1]=t.y; rbuf[q4*4+2]=t.z; rbuf[q4*4+3]=t.w;
    }
    #pragma unroll
    for (int c = 0; c < 16; c++) es[0][c*132 + tid] = rbuf[c];
    __syncthreads();

    unsigned long long acc2[8][4];
    #pragma unroll
    for (int i=0;i<8;i++)
        #pragma unroll
        for (int j=0;j<4;j++) acc2[i][j] = 0ULL;

    for (int cch = 0; cch < 8; cch++){
        const int kc  = cch << 4;
        const int buf = cch & 1;
        if (cch < 7){
            #pragma unroll
            for (int q4 = 0; q4 < 4; q4++){
                float4 t = vok ? *reinterpret_cast<const float4*>(erow + kc + 16 + (q4<<2))
                               : make_float4(0.f,0.f,0.f,0.f);
                rbuf[q4*4+0]=t.x; rbuf[q4*4+1]=t.y; rbuf[q4*4+2]=t.z; rbuf[q4*4+3]=t.w;
            }
        }
        #pragma unroll
        for (int kk = 0; kk < 16; kk++){
            float4 e0 = *reinterpret_cast<const float4*>(&es[buf][kk*132 + (tv<<2)]);
            float4 e1 = *reinterpret_cast<const float4*>(&es[buf][kk*132 + 64 + (tv<<2)]);
            float4 a0 = *reinterpret_cast<const float4*>(&qs[(kc+kk)*68 + (tn<<2)]);
            float4 a1 = *reinterpret_cast<const float4*>(&qs[(kc+kk)*68 + 32 + (tn<<2)]);
            unsigned long long qp0 = pack2(a0.x, a0.y);
            unsigned long long qp1 = pack2(a0.z, a0.w);
            unsigned long long qp2 = pack2(a1.x, a1.y);
            unsigned long long qp3 = pack2(a1.z, a1.w);
            float ev[8] = {e0.x,e0.y,e0.z,e0.w,e1.x,e1.y,e1.z,e1.w};
            #pragma unroll
            for (int i = 0; i < 8; i++){
                unsigned long long eb = pack2(ev[i], ev[i]);
                acc2[i][0] = fma2(eb, qp0, acc2[i][0]);
                acc2[i][1] = fma2(eb, qp1, acc2[i][1]);
                acc2[i][2] = fma2(eb, qp2, acc2[i][2]);
                acc2[i][3] = fma2(eb, qp3, acc2[i][3]);
            }
        }
        if (cch < 7){
            #pragma unroll
            for (int c = 0; c < 16; c++) es[buf^1][c*132 + tid] = rbuf[c];
        }
        __syncthreads();
    }

    // ---- epilogue: masked softmax-weighted sum over n + adot (n==50) ----
    const int lane  = tid & 31;
    const int gbase = lane & ~7;
    // per-thread n indices: f[0..3] -> tn*4+{0..3}, f[4..7] -> 32+tn*4+{0..3}
    int nidx[8];
    #pragma unroll
    for (int e = 0; e < 4; e++){ nidx[e] = (tn<<2)+e; nidx[4+e] = 32+(tn<<2)+e; }
    bool valid[8];
    #pragma unroll
    for (int e = 0; e < 8; e++) valid[e] = (nidx[e] < N_) && msk[nidx[e]];

    #pragma unroll
    for (int i = 0; i < 8; i++){
        float f[8];
        #pragma unroll
        for (int j = 0; j < 4; j++){ f[2*j] = lo2(acc2[i][j]); f[2*j+1] = hi2(acc2[i][j]); }
        // n == 50 lives at tn==4, f[6]
        float adot = __shfl_sync(0xffffffffu, f[6], gbase + 4);
        float mx = -3.0e38f;
        #pragma unroll
        for (int e = 0; e < 8; e++) if (valid[e]) mx = fmaxf(mx, f[e]);
        mx = fmaxf(mx, __shfl_xor_sync(0xffffffffu, mx, 1));
        mx = fmaxf(mx, __shfl_xor_sync(0xffffffffu, mx, 2));
        mx = fmaxf(mx, __shfl_xor_sync(0xffffffffu, mx, 4));
        float se = 0.f, sw = 0.f;
        #pragma unroll
        for (int e = 0; e < 8; e++){
            if (valid[e]){
                float ex = __expf(f[e] - mx);
                se += ex;
                sw = fmaf(ex, f[e], sw);
            }
        }
        se += __shfl_xor_sync(0xffffffffu, se, 1);
        sw += __shfl_xor_sync(0xffffffffu, sw, 1);
        se += __shfl_xor_sync(0xffffffffu, se, 2);
        sw += __shfl_xor_sync(0xffffffffu, sw, 2);
        se += __shfl_xor_sync(0xffffffffu, se, 4);
        sw += __shfl_xor_sync(0xffffffffu, sw, 4);
        if (tn == 0){
            int vl = (i < 4) ? ((tv<<2) + i) : (64 + (tv<<2) + (i-4));
            int v  = v0 + vl;
            if (v < VM1) out[(size_t)b*VM1 + v] = sw/se + adot;
        }
    }
}

// ---------------- host side ----------------
static float* symaddr(const void* sym){
    void* p = nullptr;
    cudaGetSymbolAddress(&p, sym);
    return (float*)p;
}

static void gemm(const float* X, const float* W, const float* bias, float* out,
                 int R, int K, int J){
    dim3 g((J + 63) / 64, (R + 63) / 64);
    k_gemm_tn<<<g, 256>>>(X, W, bias, out, R, K, J);
}

extern "C" void kernel_launch(void* const* d_in, const int* in_sizes, int n_in,
                              void* d_out, int out_size){
    (void)in_sizes; (void)n_in; (void)out_size;
    const int*   items  = (const int*)  d_in[0];
    const float* A      = (const float*)d_in[1];
    const int*   mask   = (const int*)  d_in[2];
    const float* emb    = (const float*)d_in[3];
    const float* w_ih   = (const float*)d_in[4];
    const float* w_hh   = (const float*)d_in[5];
    const float* b_ih   = (const float*)d_in[6];
    const float* b_hh   = (const float*)d_in[7];
    const float* b_iah  = (const float*)d_in[8];
    const float* b_oah  = (const float*)d_in[9];
    const float* W_ein  = (const float*)d_in[10];
    const float* b_ein  = (const float*)d_in[11];
    const float* W_eout = (const float*)d_in[12];
    const float* b_eout = (const float*)d_in[13];
    const float* W_one  = (const float*)d_in[14];
    const float* b_one  = (const float*)d_in[15];
    const float* W_two  = (const float*)d_in[16];
    const float* b_two  = (const float*)d_in[17];
    const float* w_three= (const float*)d_in[18];
    const float* W_tr   = (const float*)d_in[19];
    const float* b_tr   = (const float*)d_in[20];
    const float* W_t    = (const float*)d_in[21];
    float* out = (float*)d_out;

    float* hidden = symaddr(g_hidden);
    float* ein    = symaddr(g_ein);
    float* eout   = symaddr(g_eout);
    float* inputs = symaddr(g_inputs);
    float* ht     = symaddr(g_ht);
    float* q1     = symaddr(g_q1);
    float* q2     = symaddr(g_q2);
    float* cat    = symaddr(g_cat);
    float* a      = symaddr(g_a);
    float* hm     = symaddr(g_hm);
    float* qt     = symaddr(g_qt);
    float* qtpad  = symaddr(g_qtpad);

    // embedding gather
    k_gather<<<R_, H_>>>(items, emb, hidden);

    // 2 GNN steps
    for (int step = 0; step < 2; step++){
        dim3 g2(2, 13);
        k_gemm2<<<g2, 256>>>(hidden, W_ein, b_ein, W_eout, b_eout, ein, eout);
        k_prop<<<R_, H_>>>(A, ein, eout, b_iah, b_oah, inputs);
        k_gru<<<R_/8, 256>>>(inputs, hidden, w_ih, w_hh, b_ih, b_hh);
    }

    // attention head
    k_ht<<<B_, H_>>>(mask, hidden, ht);
    gemm(ht,     W_one, b_one, q1, B_, H_, H_);
    gemm(hidden, W_two, b_two, q2, R_, H_, H_);
    k_alpha<<<B_, H_>>>(q1, q2, w_three, mask, hidden, ht, cat);
    gemm(cat, W_tr, b_tr, a, B_, 2*H_, H_);
    k_maskmul<<<R_, H_>>>(hidden, mask, hm);
    gemm(hm, W_t, nullptr, qt, R_, H_, H_);
    k_pack<<<B_*64, H_>>>(qt, a, qtpad);

    // fused vocab scoring
    dim3 sg((VM1 + 127) / 128, B_);
    k_scores<<<sg, 128>>>(emb, qtpad, mask, out);
}

// round 5
// speedup vs baseline: 1.9081x; 1.1165x over previous
#include <cuda_runtime.h>
#include <cuda_bf16.h>
#include <math.h>

// Problem constants
#define B_  16
#define N_  50
#define H_  128
#define V_  40000
#define VM1 39999      // V-1 rows of b_emb / output columns
#define R_  (B_*N_)    // 800 rows
#define NT_ 313        // ceil(VM1/128) vocab tiles (128 rows each)

// ---------------- scratch (static __device__, no allocs) ----------------
__device__ float g_hidden[R_*H_];
__device__ float g_ein   [R_*H_];
__device__ float g_eout  [R_*H_];
__device__ float g_inputs[R_*2*H_];
__device__ float g_S     [R_*3*H_];
__device__ float g_hn    [R_*H_];
__device__ float g_ht    [B_*H_];
__device__ float g_q1    [B_*H_];
__device__ float g_q2    [R_*H_];
__device__ float g_cat   [B_*2*H_];
__device__ float g_a     [B_*H_];
__device__ float g_hm    [R_*H_];
__device__ float g_qt    [R_*H_];
// HMMA staging: bf16 hi/lo split, ldmatrix XOR-chunk swizzled layouts
// emb tile t: 128 rows x 128 k (bf16) = 32768 B per tile per component
__device__ unsigned char g_embh[(size_t)NT_*32768];
__device__ unsigned char g_embl[(size_t)NT_*32768];
// q tile b: 64 n-rows x 128 k (bf16) = 16384 B per batch per component
__device__ unsigned char g_qbh [B_*16384];
__device__ unsigned char g_qbl [B_*16384];
__device__ int g_len[B_];

// ---------------- small helpers ----------------
__device__ __forceinline__ float sigmoidf_(float x){ return 1.f/(1.f+expf(-x)); }

__device__ __forceinline__ unsigned smem_u32(const void* p){
    unsigned a;
    asm("{ .reg .u64 t; cvta.to.shared.u64 t, %1; cvt.u32.u64 %0, t; }" : "=r"(a) : "l"(p));
    return a;
}
__device__ __forceinline__ unsigned bf16pair(float a, float b){
    __nv_bfloat162 t = __floats2bfloat162_rn(a, b);
    return *reinterpret_cast<unsigned*>(&t);
}
__device__ __forceinline__ float bf16of(float x){
    return __bfloat162float(__float2bfloat16(x));
}

__device__ __forceinline__ void ldsm4(unsigned& r0, unsigned& r1, unsigned& r2, unsigned& r3,
                                      unsigned addr){
    asm volatile("ldmatrix.sync.aligned.m8n8.x4.shared.b16 {%0,%1,%2,%3}, [%4];"
                 : "=r"(r0),"=r"(r1),"=r"(r2),"=r"(r3) : "r"(addr));
}
__device__ __forceinline__ void mma16816(float* c, unsigned a0, unsigned a1, unsigned a2,
                                         unsigned a3, unsigned b0, unsigned b1){
    asm volatile(
        "mma.sync.aligned.m16n8k16.row.col.f32.bf16.bf16.f32 "
        "{%0,%1,%2,%3}, {%4,%5,%6,%7}, {%8,%9}, {%0,%1,%2,%3};"
        : "+f"(c[0]), "+f"(c[1]), "+f"(c[2]), "+f"(c[3])
        : "r"(a0), "r"(a1), "r"(a2), "r"(a3), "r"(b0), "r"(b1));
}

// ---------------- gather: hidden = emb[items] ----------------
__global__ void k_gather(const int* __restrict__ items, const float* __restrict__ emb,
                         float* __restrict__ hidden){
    int r = blockIdx.x, h = threadIdx.x;
    hidden[r*H_ + h] = emb[(size_t)items[r]*H_ + h];
}

// ---------------- generic small GEMM: out[r,j] = sum_k X[r,k]*W[j,k] + bias[j] ----------------
__global__ void k_gemm_tn(const float* __restrict__ X, const float* __restrict__ W,
                          const float* __restrict__ bias, float* __restrict__ out,
                          int R, int K, int J){
    __shared__ float xs[16][65];
    __shared__ float ws[16][65];
    int tid = threadIdx.x;
    int tr = tid >> 4, tc = tid & 15;
    int r0 = blockIdx.y << 6, j0 = blockIdx.x << 6;
    float acc[4][4] = {};
    for (int kc = 0; kc < K; kc += 16){
        for (int t = tid; t < 1024; t += 256){
            int rr = t >> 4, kk = t & 15;
            int r = r0 + rr;
            xs[kk][rr] = (r < R) ? X[(size_t)r*K + kc + kk] : 0.f;
        }
        for (int t = tid; t < 1024; t += 256){
            int jj = t >> 4, kk = t & 15;
            int j = j0 + jj;
            ws[kk][jj] = (j < J) ? W[(size_t)j*K + kc + kk] : 0.f;
        }
        __syncthreads();
        #pragma unroll
        for (int kk = 0; kk < 16; kk++){
            float xv[4], wv[4];
            #pragma unroll
            for (int i=0;i<4;i++) xv[i] = xs[kk][(tr<<2)+i];
            #pragma unroll
            for (int j=0;j<4;j++) wv[j] = ws[kk][(tc<<2)+j];
            #pragma unroll
            for (int i=0;i<4;i++)
                #pragma unroll
                for (int j=0;j<4;j++)
                    acc[i][j] = fmaf(xv[i], wv[j], acc[i][j]);
        }
        __syncthreads();
    }
    #pragma unroll
    for (int i=0;i<4;i++){
        int r = r0 + (tr<<2) + i;
        if (r >= R) continue;
        #pragma unroll
        for (int j=0;j<4;j++){
            int jj = j0 + (tc<<2) + j;
            if (jj < J) out[(size_t)r*J + jj] = acc[i][j] + (bias ? bias[jj] : 0.f);
        }
    }
}

// ---------------- fused two-output GEMM for ein/eout (R=800, K=J=128) ----------------
__global__ void k_gemm2(const float* __restrict__ X,
                        const float* __restrict__ W1, const float* __restrict__ b1,
                        const float* __restrict__ W2, const float* __restrict__ b2,
                        float* __restrict__ out1, float* __restrict__ out2){
    __shared__ float xs [16][65];
    __shared__ float ws1[16][65];
    __shared__ float ws2[16][65];
    int tid = threadIdx.x;
    int tr = tid >> 4, tc = tid & 15;
    int r0 = blockIdx.y << 6, j0 = blockIdx.x << 6;
    float acc1[4][4] = {}, acc2_[4][4] = {};
    for (int kc = 0; kc < H_; kc += 16){
        for (int t = tid; t < 1024; t += 256){
            int rr = t >> 4, kk = t & 15;
            int r = r0 + rr;
            xs[kk][rr] = (r < R_) ? X[(size_t)r*H_ + kc + kk] : 0.f;
        }
        for (int t = tid; t < 1024; t += 256){
            int jj = t >> 4, kk = t & 15;
            ws1[kk][jj] = W1[(size_t)(j0+jj)*H_ + kc + kk];
            ws2[kk][jj] = W2[(size_t)(j0+jj)*H_ + kc + kk];
        }
        __syncthreads();
        #pragma unroll
        for (int kk = 0; kk < 16; kk++){
            float xv[4], w1v[4], w2v[4];
            #pragma unroll
            for (int i=0;i<4;i++) xv[i] = xs[kk][(tr<<2)+i];
            #pragma unroll
            for (int j=0;j<4;j++){ w1v[j] = ws1[kk][(tc<<2)+j]; w2v[j] = ws2[kk][(tc<<2)+j]; }
            #pragma unroll
            for (int i=0;i<4;i++)
                #pragma unroll
                for (int j=0;j<4;j++){
                    acc1[i][j]  = fmaf(xv[i], w1v[j], acc1[i][j]);
                    acc2_[i][j] = fmaf(xv[i], w2v[j], acc2_[i][j]);
                }
        }
        __syncthreads();
    }
    #pragma unroll
    for (int i=0;i<4;i++){
        int r = r0 + (tr<<2) + i;
        if (r >= R_) continue;
        #pragma unroll
        for (int j=0;j<4;j++){
            int jj = j0 + (tc<<2) + j;
            out1[(size_t)r*H_ + jj] = acc1[i][j]  + b1[jj];
            out2[(size_t)r*H_ + jj] = acc2_[i][j] + b2[jj];
        }
    }
}

// ---------------- graph propagation ----------------
__global__ void k_prop(const float* __restrict__ A, const float* __restrict__ ein,
                       const float* __restrict__ eout, const float* __restrict__ b_iah,
                       const float* __restrict__ b_oah, float* __restrict__ inputs){
    int r = blockIdx.x;                 // b*50+n
    int b = r / N_;
    int h = threadIdx.x;
    __shared__ float arow[2*N_];
    if (h < 2*N_) arow[h] = A[(size_t)r*2*N_ + h];
    __syncthreads();
    float sin = b_iah[h], sout = b_oah[h];
    #pragma unroll 5
    for (int m = 0; m < N_; m++){
        sin  = fmaf(arow[m],      ein [(b*N_+m)*H_ + h], sin);
        sout = fmaf(arow[N_+m],   eout[(b*N_+m)*H_ + h], sout);
    }
    inputs[(size_t)r*2*H_ + h]      = sin;
    inputs[(size_t)r*2*H_ + H_ + h] = sout;
}

// ---------------- GRU combined GEMM: S (800x384) and hn (800x128) in one pass ----------------
__global__ void k_gruS(const float* __restrict__ inputs, const float* __restrict__ hidden,
                       const float* __restrict__ w_ih, const float* __restrict__ w_hh,
                       const float* __restrict__ b_ih, const float* __restrict__ b_hh,
                       float* __restrict__ S, float* __restrict__ hn){
    __shared__ float xs[16][65];
    __shared__ float ws[16][65];
    int tid = threadIdx.x;
    int tr = tid >> 4, tc = tid & 15;
    int r0 = blockIdx.y << 6, j0 = blockIdx.x << 6;
    float acc[4][4] = {};
    for (int kc = 0; kc < 384; kc += 16){
        for (int t = tid; t < 1024; t += 256){
            int rr = t >> 4, kk = t & 15;
            int r = r0 + rr, k = kc + kk;
            float v = 0.f;
            if (r < R_)
                v = (k < 256) ? inputs[(size_t)r*256 + k] : hidden[(size_t)r*128 + (k-256)];
            xs[kk][rr] = v;
        }
        for (int t = tid; t < 1024; t += 256){
            int jj = t >> 4, kk = t & 15;
            int j = j0 + jj, k = kc + kk;
            float w;
            if (j < 384) w = (k < 256) ? w_ih[(size_t)j*256 + k]
                                       : w_hh[(size_t)j*128 + (k-256)];
            else         w = (k < 256) ? 0.f
                                       : w_hh[(size_t)(256 + j - 384)*128 + (k-256)];
            ws[kk][jj] = w;
        }
        __syncthreads();
        #pragma unroll
        for (int kk = 0; kk < 16; kk++){
            float xv[4], wv[4];
            #pragma unroll
            for (int i=0;i<4;i++) xv[i] = xs[kk][(tr<<2)+i];
            #pragma unroll
            for (int j=0;j<4;j++) wv[j] = ws[kk][(tc<<2)+j];
            #pragma unroll
            for (int i=0;i<4;i++)
                #pragma unroll
                for (int j=0;j<4;j++)
                    acc[i][j] = fmaf(xv[i], wv[j], acc[i][j]);
        }
        __syncthreads();
    }
    #pragma unroll
    for (int i=0;i<4;i++){
        int r = r0 + (tr<<2) + i;
        if (r >= R_) continue;
        #pragma unroll
        for (int j=0;j<4;j++){
            int jj = j0 + (tc<<2) + j;
            if (jj < 384) S [(size_t)r*384 + jj]       = acc[i][j] + b_ih[jj] + b_hh[jj];
            else          hn[(size_t)r*128 + (jj-384)] = acc[i][j] + b_hh[256 + jj - 384];
        }
    }
}

// ---------------- GRU gate: i_n = S_n - hn ----------------
__global__ void k_gate2(const float* __restrict__ S, const float* __restrict__ hn,
                        float* __restrict__ hidden){
    int r = blockIdx.x, h = threadIdx.x;
    float sr = S[(size_t)r*384 + h];
    float si = S[(size_t)r*384 + 128 + h];
    float sn = S[(size_t)r*384 + 256 + h];
    float hv_n = hn[(size_t)r*128 + h];
    float rg = sigmoidf_(sr);
    float ig = sigmoidf_(si);
    float ng = tanhf(sn - hv_n + rg * hv_n);
    float hv = hidden[(size_t)r*H_ + h];
    hidden[(size_t)r*H_ + h] = ng + ig * (hv - ng);
}

// ---------------- ht = hidden[b, len-1] ----------------
__global__ void k_ht(const int* __restrict__ mask, const float* __restrict__ hidden,
                     float* __restrict__ ht){
    int b = blockIdx.x;
    __shared__ int len;
    if (threadIdx.x == 0){
        int s = 0;
        for (int n = 0; n < N_; n++) s += mask[b*N_+n];
        len = s;
    }
    __syncthreads();
    int h = threadIdx.x;
    ht[b*H_ + h] = hidden[(b*N_ + len - 1)*H_ + h];
}

// ---------------- alpha attention + cat = [avec, ht] ----------------
__global__ void k_alpha(const float* __restrict__ q1, const float* __restrict__ q2,
                        const float* __restrict__ w3, const int* __restrict__ mask,
                        const float* __restrict__ hidden, const float* __restrict__ ht,
                        float* __restrict__ cat){
    int b = blockIdx.x, tid = threadIdx.x;
    __shared__ float logits[N_];
    int warp = tid >> 5, lane = tid & 31;
    for (int n = warp; n < N_; n += 4){
        float s = 0.f;
        for (int hh = lane; hh < H_; hh += 32){
            float x = q1[b*H_+hh] + q2[(b*N_+n)*H_ + hh];
            s += sigmoidf_(x) * w3[hh];
        }
        for (int d = 16; d; d >>= 1) s += __shfl_xor_sync(0xffffffffu, s, d);
        if (lane == 0) logits[n] = s;
    }
    __syncthreads();
    float mx = -3.0e38f;
    for (int n = 0; n < N_; n++) if (mask[b*N_+n]) mx = fmaxf(mx, logits[n]);
    float denom = 0.f;
    for (int n = 0; n < N_; n++) if (mask[b*N_+n]) denom += expf(logits[n]-mx);
    int h = tid;
    float s = 0.f;
    for (int n = 0; n < N_; n++)
        if (mask[b*N_+n]) s = fmaf(expf(logits[n]-mx), hidden[(b*N_+n)*H_ + h], s);
    cat[b*2*H_ + h]      = s / denom;
    cat[b*2*H_ + H_ + h] = ht[b*H_ + h];
}

// ---------------- hm = hidden * mask ----------------
__global__ void k_maskmul(const float* __restrict__ hidden, const int* __restrict__ mask,
                          float* __restrict__ hm){
    int r = blockIdx.x, h = threadIdx.x;
    hm[r*H_ + h] = mask[r] ? hidden[r*H_ + h] : 0.f;
}

// ---------------- prep: emb -> bf16 hi/lo tiles, ldmatrix XOR-chunk swizzle ----------------
// Layout: tile t, row r (0..127), chunk c (0..15, 16B each holding k = c*8..c*8+7):
// byte offset = ((t*128 + r)*16 + (c ^ (r&7)))*16
__global__ void k_prep_emb(const float* __restrict__ emb){
    int t = blockIdx.x, r = threadIdx.x;
    int vg = t*128 + r;
    bool ok = vg < VM1;
    const float4* src = reinterpret_cast<const float4*>(emb + (size_t)(vg+1)*H_);
    uint4* dh = reinterpret_cast<uint4*>(g_embh);
    uint4* dl = reinterpret_cast<uint4*>(g_embl);
    size_t rb = ((size_t)t*128 + r)*16;
    #pragma unroll
    for (int c = 0; c < 16; c++){
        float4 f0 = ok ? src[2*c]   : make_float4(0.f,0.f,0.f,0.f);
        float4 f1 = ok ? src[2*c+1] : make_float4(0.f,0.f,0.f,0.f);
        uint4 hi, lo;
        hi.x = bf16pair(f0.x, f0.y); hi.y = bf16pair(f0.z, f0.w);
        hi.z = bf16pair(f1.x, f1.y); hi.w = bf16pair(f1.z, f1.w);
        lo.x = bf16pair(f0.x - bf16of(f0.x), f0.y - bf16of(f0.y));
        lo.y = bf16pair(f0.z - bf16of(f0.z), f0.w - bf16of(f0.w));
        lo.z = bf16pair(f1.x - bf16of(f1.x), f1.y - bf16of(f1.y));
        lo.w = bf16pair(f1.z - bf16of(f1.z), f1.w - bf16of(f1.w));
        size_t o = rb + (c ^ (r & 7));
        dh[o] = hi;
        dl[o] = lo;
    }
}

// ---------------- pack qt/a -> per-batch B tiles (64 x 128) bf16 hi/lo + lengths ----------------
__global__ void k_pack_tc(const float* __restrict__ qt, const float* __restrict__ a,
                          const int* __restrict__ mask){
    int b = blockIdx.x, n = threadIdx.x;   // 64 threads
    const float* src = (n < N_) ? (qt + (size_t)(b*N_+n)*H_)
                 : (n == N_)    ? (a  + (size_t)b*H_) : nullptr;
    uint4* dh = reinterpret_cast<uint4*>(g_qbh);
    uint4* dl = reinterpret_cast<uint4*>(g_qbl);
    size_t rb = ((size_t)b*64 + n)*16;
    #pragma unroll
    for (int c = 0; c < 16; c++){
        float4 f0 = src ? *reinterpret_cast<const float4*>(src + c*8)     : make_float4(0.f,0.f,0.f,0.f);
        float4 f1 = src ? *reinterpret_cast<const float4*>(src + c*8 + 4) : make_float4(0.f,0.f,0.f,0.f);
        uint4 hi, lo;
        hi.x = bf16pair(f0.x, f0.y); hi.y = bf16pair(f0.z, f0.w);
        hi.z = bf16pair(f1.x, f1.y); hi.w = bf16pair(f1.z, f1.w);
        lo.x = bf16pair(f0.x - bf16of(f0.x), f0.y - bf16of(f0.y));
        lo.y = bf16pair(f0.z - bf16of(f0.z), f0.w - bf16of(f0.w));
        lo.z = bf16pair(f1.x - bf16of(f1.x), f1.y - bf16of(f1.y));
        lo.w = bf16pair(f1.z - bf16of(f1.z), f1.w - bf16of(f1.w));
        size_t o = rb + (c ^ (n & 7));
        dh[o] = hi;
        dl[o] = lo;
    }
    if (n == 0){
        int s = 0;
        for (int i = 0; i < N_; i++) s += mask[b*N_+i];
        g_len[b] = s;
    }
}

// ---------------- HMMA vocab scoring ----------------
// grid 313, 256 threads (8 warps), 96KB dyn smem. Warp w owns rows [w*16, w*16+16).
// D[v,n] = emb[v]·qt[n] via 3-pass bf16 split; masked softmax epilogue per v-row.
#define SC_AH 0
#define SC_AL 32768
#define SC_BH 65536
#define SC_BL 81920
#define SC_BYTES 98304

__global__ void __launch_bounds__(256, 2)
k_scores_mma(float* __restrict__ out){
    extern __shared__ char sm[];
    unsigned sbase = smem_u32(sm);
    const int tid = threadIdx.x, wid = tid >> 5, lane = tid & 31;
    const int t = blockIdx.x;

    // stage A tiles (pre-swizzled): 32KB hi + 32KB lo
    {
        const uint4* sh = reinterpret_cast<const uint4*>(g_embh + (size_t)t*32768);
        const uint4* sl = reinterpret_cast<const uint4*>(g_embl + (size_t)t*32768);
        uint4* dh = reinterpret_cast<uint4*>(sm + SC_AH);
        uint4* dl = reinterpret_cast<uint4*>(sm + SC_AL);
        #pragma unroll
        for (int i = 0; i < 8; i++){
            dh[tid + (i<<8)] = sh[tid + (i<<8)];
            dl[tid + (i<<8)] = sl[tid + (i<<8)];
        }
    }

    // per-lane ldmatrix address components
    const int r0   = wid << 4;                  // warp's row base in tile
    const int rowA = r0 + (lane & 15);
    const int phA  = rowA & 7;
    const int hl   = lane >> 4;                 // 0/1: k-chunk half selector
    const unsigned baseAh = sbase + SC_AH + rowA*256;
    const unsigned baseAl = sbase + SC_AL + rowA*256;
    const int rowB = (lane & 15);               // + ni2*16
    const int phB0 = rowB & 7;

    for (int b = 0; b < B_; b++){
        __syncthreads();
        // stage B tiles (16KB hi + 16KB lo)
        {
            const uint4* sh = reinterpret_cast<const uint4*>(g_qbh + (size_t)b*16384);
            const uint4* sl = reinterpret_cast<const uint4*>(g_qbl + (size_t)b*16384);
            uint4* dh = reinterpret_cast<uint4*>(sm + SC_BH);
            uint4* dl = reinterpret_cast<uint4*>(sm + SC_BL);
            #pragma unroll
            for (int i = 0; i < 4; i++){
                dh[tid + (i<<8)] = sh[tid + (i<<8)];
                dl[tid + (i<<8)] = sl[tid + (i<<8)];
            }
        }
        __syncthreads();
        const int len = g_len[b];

        float acc[8][4];
        #pragma unroll
        for (int ni = 0; ni < 8; ni++)
            #pragma unroll
            for (int e = 0; e < 4; e++) acc[ni][e] = 0.f;

        #pragma unroll
        for (int ks = 0; ks < 8; ks++){
            unsigned ah[4], al[4];
            unsigned offA = (unsigned)(((ks*2 + hl) ^ phA) << 4);
            ldsm4(ah[0], ah[1], ah[2], ah[3], baseAh + offA);
            ldsm4(al[0], al[1], al[2], al[3], baseAl + offA);
            unsigned bh[8][2], bl[8][2];
            #pragma unroll
            for (int ni2 = 0; ni2 < 4; ni2++){
                if (ni2*16 < len + 8 || ni2 == 3){   // tile pair needed? (keeps ni=6,7 pair)
                    unsigned offB = (unsigned)((ni2*16 + rowB)*256 + (((ks*2 + hl) ^ phB0) << 4));
                    unsigned q0,q1,q2,q3;
                    ldsm4(q0,q1,q2,q3, sbase + SC_BH + offB);
                    bh[2*ni2][0]=q0; bh[2*ni2][1]=q2; bh[2*ni2+1][0]=q1; bh[2*ni2+1][1]=q3;
                    ldsm4(q0,q1,q2,q3, sbase + SC_BL + offB);
                    bl[2*ni2][0]=q0; bl[2*ni2][1]=q2; bl[2*ni2+1][0]=q1; bl[2*ni2+1][1]=q3;
                }
            }
            #pragma unroll
            for (int ni = 0; ni < 8; ni++){
                if (ni*8 < len || ni == 6){      // skip fully-masked N-tiles (keep adot tile)
                    mma16816(acc[ni], ah[0],ah[1],ah[2],ah[3], bh[ni][0], bh[ni][1]);
                    mma16816(acc[ni], ah[0],ah[1],ah[2],ah[3], bl[ni][0], bl[ni][1]);
                    mma16816(acc[ni], al[0],al[1],al[2],al[3], bh[ni][0], bh[ni][1]);
                }
            }
        }

        // epilogue: per v-row masked softmax-weighted sum + adot (col 50)
        const int q1lane = (lane & ~3) | 1;      // holds col 50 (ni=6, colpair base 2)
        float ad0 = __shfl_sync(0xffffffffu, acc[6][0], q1lane);
        float ad8 = __shfl_sync(0xffffffffu, acc[6][2], q1lane);
        const int cb = (lane & 3) << 1;          // col base within n8 tile
        #pragma unroll
        for (int rh = 0; rh < 2; rh++){
            float mx = -3.0e38f;
            #pragma unroll
            for (int ni = 0; ni < 8; ni++){
                if (ni*8 < len){
                    #pragma unroll
                    for (int e = 0; e < 2; e++){
                        int n = ni*8 + cb + e;
                        if (n < len) mx = fmaxf(mx, acc[ni][rh*2+e]);
                    }
                }
            }
            mx = fmaxf(mx, __shfl_xor_sync(0xffffffffu, mx, 1));
            mx = fmaxf(mx, __shfl_xor_sync(0xffffffffu, mx, 2));
            float se = 0.f, sw = 0.f;
            #pragma unroll
            for (int ni = 0; ni < 8; ni++){
                if (ni*8 < len){
                    #pragma unroll
                    for (int e = 0; e < 2; e++){
                        int n = ni*8 + cb + e;
                        if (n < len){
                            float f = acc[ni][rh*2+e];
                            float ex = __expf(f - mx);
                            se += ex;
                            sw = fmaf(ex, f, sw);
                        }
                    }
                }
            }
            se += __shfl_xor_sync(0xffffffffu, se, 1);
            sw += __shfl_xor_sync(0xffffffffu, sw, 1);
            se += __shfl_xor_sync(0xffffffffu, se, 2);
            sw += __shfl_xor_sync(0xffffffffu, sw, 2);
            if ((lane & 3) == 0){
                int v = t*128 + r0 + (lane >> 2) + rh*8;
                if (v < VM1) out[(size_t)b*VM1 + v] = sw/se + (rh ? ad8 : ad0);
            }
        }
    }
}

// ---------------- host side ----------------
static float* symaddr(const void* sym){
    void* p = nullptr;
    cudaGetSymbolAddress(&p, sym);
    return (float*)p;
}

static void gemm(const float* X, const float* W, const float* bias, float* out,
                 int R, int K, int J){
    dim3 g((J + 63) / 64, (R + 63) / 64);
    k_gemm_tn<<<g, 256>>>(X, W, bias, out, R, K, J);
}

extern "C" void kernel_launch(void* const* d_in, const int* in_sizes, int n_in,
                              void* d_out, int out_size){
    (void)in_sizes; (void)n_in; (void)out_size;
    const int*   items  = (const int*)  d_in[0];
    const float* A      = (const float*)d_in[1];
    const int*   mask   = (const int*)  d_in[2];
    const float* emb    = (const float*)d_in[3];
    const float* w_ih   = (const float*)d_in[4];
    const float* w_hh   = (const float*)d_in[5];
    const float* b_ih   = (const float*)d_in[6];
    const float* b_hh   = (const float*)d_in[7];
    const float* b_iah  = (const float*)d_in[8];
    const float* b_oah  = (const float*)d_in[9];
    const float* W_ein  = (const float*)d_in[10];
    const float* b_ein  = (const float*)d_in[11];
    const float* W_eout = (const float*)d_in[12];
    const float* b_eout = (const float*)d_in[13];
    const float* W_one  = (const float*)d_in[14];
    const float* b_one  = (const float*)d_in[15];
    const float* W_two  = (const float*)d_in[16];
    const float* b_two  = (const float*)d_in[17];
    const float* w_three= (const float*)d_in[18];
    const float* W_tr   = (const float*)d_in[19];
    const float* b_tr   = (const float*)d_in[20];
    const float* W_t    = (const float*)d_in[21];
    float* out = (float*)d_out;

    float* hidden = symaddr(g_hidden);
    float* ein    = symaddr(g_ein);
    float* eout   = symaddr(g_eout);
    float* inputs = symaddr(g_inputs);
    float* S      = symaddr(g_S);
    float* hn     = symaddr(g_hn);
    float* ht     = symaddr(g_ht);
    float* q1     = symaddr(g_q1);
    float* q2     = symaddr(g_q2);
    float* cat    = symaddr(g_cat);
    float* a      = symaddr(g_a);
    float* hm     = symaddr(g_hm);
    float* qt     = symaddr(g_qt);

    static int smem_set = 0;
    if (!smem_set){
        cudaFuncSetAttribute(k_scores_mma, cudaFuncAttributeMaxDynamicSharedMemorySize, SC_BYTES);
        smem_set = 1;
    }

    // prep emb bf16 tiles (independent of GNN chain)
    k_prep_emb<<<NT_, 128>>>(emb);

    // embedding gather
    k_gather<<<R_, H_>>>(items, emb, hidden);

    // 2 GNN steps
    for (int step = 0; step < 2; step++){
        dim3 g2(2, 13);
        k_gemm2<<<g2, 256>>>(hidden, W_ein, b_ein, W_eout, b_eout, ein, eout);
        k_prop<<<R_, H_>>>(A, ein, eout, b_iah, b_oah, inputs);
        dim3 gs(8, 13);
        k_gruS<<<gs, 256>>>(inputs, hidden, w_ih, w_hh, b_ih, b_hh, S, hn);
        k_gate2<<<R_, H_>>>(S, hn, hidden);
    }

    // attention head
    k_ht<<<B_, H_>>>(mask, hidden, ht);
    gemm(ht,     W_one, b_one, q1, B_, H_, H_);
    gemm(hidden, W_two, b_two, q2, R_, H_, H_);
    k_alpha<<<B_, H_>>>(q1, q2, w_three, mask, hidden, ht, cat);
    gemm(cat, W_tr, b_tr, a, B_, 2*H_, H_);
    k_maskmul<<<R_, H_>>>(hidden, mask, hm);
    gemm(hm, W_t, nullptr, qt, R_, H_, H_);
    k_pack_tc<<<B_, 64>>>(qt, a, mask);

    // HMMA vocab scoring
    k_scores_mma<<<NT_, 256, SC_BYTES>>>(out);
}